// round 1
// baseline (speedup 1.0000x reference)
#include <cuda_runtime.h>
#include <cstdint>
#include <cstdio>

// Problem constants
#define MTOK  16128          // B*L = 8*2016
#define Dm    256
#define Lseq  2016
#define Hh    4
#define LPAD  2020           // padded logit row stride (mult of 4, !=0 mod 32)
#define QSCALE 0.0625f       // 1/sqrt(256)

// Scratch (static device globals; no allocation allowed)
__device__ float g_h[MTOK * Dm];
__device__ float g_q[MTOK * 128];
__device__ float g_k[MTOK * 128];
__device__ float g_v[MTOK * 128];
__device__ float g_o[MTOK * 128];
__device__ float g_t[MTOK * Dm];
__device__ float g_f[MTOK * 64];

// ---------------------------------------------------------------------------
// Input projection: h = x @ in_w + in_b   (K=2, trivial)
// ---------------------------------------------------------------------------
__global__ void inproj_kernel(const float* __restrict__ x, const float* __restrict__ w,
                              const float* __restrict__ b, float* __restrict__ h) {
    int idx = blockIdx.x * 256 + threadIdx.x;
    if (idx >= MTOK * Dm) return;
    int tok = idx >> 8, d = idx & 255;
    h[idx] = fmaf(x[2 * tok], w[d], fmaf(x[2 * tok + 1], w[256 + d], b[d]));
}

// ---------------------------------------------------------------------------
// Generic SGEMM: C[M,N] = A[M,K] @ W[K,N] + bias (+ optional relu)
// Requires M%64==0, N%64==0, K%16==0. 64x64 tile, BK=16, 256 thr, 4x4 microtile.
// ---------------------------------------------------------------------------
__global__ __launch_bounds__(256) void sgemm_kernel(
    const float* __restrict__ A, const float* __restrict__ W,
    const float* __restrict__ bias, float* __restrict__ C,
    int M, int N, int K, int relu)
{
    __shared__ float As[16][68];   // [k][m], padded
    __shared__ float Ws[16][64];   // [k][n]
    const int t = threadIdx.x;
    const int bm = blockIdx.x * 64, bn = blockIdx.y * 64;
    const int tx = t & 15, ty = t >> 4;
    const int ar = t >> 2, ac = (t & 3) * 4;
    const int wr = t >> 4, wc = (t & 15) * 4;
    float acc[4][4] = {};

    for (int k0 = 0; k0 < K; k0 += 16) {
        float4 av = *(const float4*)(A + (size_t)(bm + ar) * K + k0 + ac);
        float4 wv = *(const float4*)(W + (size_t)(k0 + wr) * N + bn + wc);
        As[ac + 0][ar] = av.x; As[ac + 1][ar] = av.y;
        As[ac + 2][ar] = av.z; As[ac + 3][ar] = av.w;
        *(float4*)(&Ws[wr][wc]) = wv;
        __syncthreads();
#pragma unroll
        for (int k = 0; k < 16; k++) {
            float4 a4 = *(const float4*)(&As[k][ty * 4]);
            float4 w4 = *(const float4*)(&Ws[k][tx * 4]);
            acc[0][0] = fmaf(a4.x, w4.x, acc[0][0]); acc[0][1] = fmaf(a4.x, w4.y, acc[0][1]);
            acc[0][2] = fmaf(a4.x, w4.z, acc[0][2]); acc[0][3] = fmaf(a4.x, w4.w, acc[0][3]);
            acc[1][0] = fmaf(a4.y, w4.x, acc[1][0]); acc[1][1] = fmaf(a4.y, w4.y, acc[1][1]);
            acc[1][2] = fmaf(a4.y, w4.z, acc[1][2]); acc[1][3] = fmaf(a4.y, w4.w, acc[1][3]);
            acc[2][0] = fmaf(a4.z, w4.x, acc[2][0]); acc[2][1] = fmaf(a4.z, w4.y, acc[2][1]);
            acc[2][2] = fmaf(a4.z, w4.z, acc[2][2]); acc[2][3] = fmaf(a4.z, w4.w, acc[2][3]);
            acc[3][0] = fmaf(a4.w, w4.x, acc[3][0]); acc[3][1] = fmaf(a4.w, w4.y, acc[3][1]);
            acc[3][2] = fmaf(a4.w, w4.z, acc[3][2]); acc[3][3] = fmaf(a4.w, w4.w, acc[3][3]);
        }
        __syncthreads();
    }
    float b0 = bias[bn + tx * 4 + 0], b1 = bias[bn + tx * 4 + 1];
    float b2 = bias[bn + tx * 4 + 2], b3 = bias[bn + tx * 4 + 3];
#pragma unroll
    for (int i = 0; i < 4; i++) {
        float4 o;
        o.x = acc[i][0] + b0; o.y = acc[i][1] + b1;
        o.z = acc[i][2] + b2; o.w = acc[i][3] + b3;
        if (relu) {
            o.x = fmaxf(o.x, 0.f); o.y = fmaxf(o.y, 0.f);
            o.z = fmaxf(o.z, 0.f); o.w = fmaxf(o.w, 0.f);
        }
        *(float4*)(C + (size_t)(bm + ty * 4 + i) * N + bn + tx * 4) = o;
    }
}

// ---------------------------------------------------------------------------
// Residual add + LayerNorm (D=256), one block per token, in-place into h
// ---------------------------------------------------------------------------
__global__ void add_ln_kernel(float* __restrict__ h, const float* __restrict__ t,
                              const float* __restrict__ g, const float* __restrict__ be) {
    __shared__ float red[8];
    const int row = blockIdx.x, i = threadIdx.x;
    const size_t base = (size_t)row * Dm;
    float v = h[base + i] + t[base + i];
    float s = v;
#pragma unroll
    for (int o = 16; o; o >>= 1) s += __shfl_xor_sync(0xffffffffu, s, o);
    if ((i & 31) == 0) red[i >> 5] = s;
    __syncthreads();
    float mean = 0.f;
#pragma unroll
    for (int k = 0; k < 8; k++) mean += red[k];
    mean *= (1.0f / Dm);
    __syncthreads();
    float d = v - mean;
    s = d * d;
#pragma unroll
    for (int o = 16; o; o >>= 1) s += __shfl_xor_sync(0xffffffffu, s, o);
    if ((i & 31) == 0) red[i >> 5] = s;
    __syncthreads();
    float var = 0.f;
#pragma unroll
    for (int k = 0; k < 8; k++) var += red[k];
    var *= (1.0f / Dm);
    h[base + i] = d * rsqrtf(var + 1e-5f) * g[i] + be[i];
}

// ---------------------------------------------------------------------------
// Attention: one CTA = (b, h, 16-query block). Full logit rows in SMEM.
// Writes normalized probs to P (the attns output slice) and O = P @ V.
// Dynamic SMEM layout (floats): sQ[512] | sKV[4224] | sL[16*LPAD]
// ---------------------------------------------------------------------------
#define ATTN_SMEM_FLOATS (512 + 4224 + 16 * LPAD)

__global__ __launch_bounds__(256) void attn_kernel(
    const float* __restrict__ Q, const float* __restrict__ K,
    const float* __restrict__ V, float* __restrict__ P, float* __restrict__ O)
{
    extern __shared__ float sm[];
    float* sQ  = sm;           // 16x32 Q block (later reused as reduction scratch)
    float* sKV = sm + 512;     // K chunk transposed [32][132] / V chunk [128][32]
    float* sL  = sm + 4736;    // 16 logit/prob rows, stride LPAD

    const int tid = threadIdx.x;
    const int qb = blockIdx.x, hh = blockIdx.y, b = blockIdx.z;
    const int l0 = qb * 16;
    const float* qptr = Q + (size_t)b * Lseq * 128 + hh * 32;
    const float* kptr = K + (size_t)b * Lseq * 128 + hh * 32;
    const float* vptr = V + (size_t)b * Lseq * 128 + hh * 32;

    for (int i = tid; i < 512; i += 256)
        sQ[i] = qptr[(size_t)(l0 + (i >> 5)) * 128 + (i & 31)];

    // ---- logits: S = Q K^T * scale, 128-key chunks through SMEM ----
    const int qg = tid >> 5;           // 0..7 -> rows 2qg, 2qg+1
    const int jj4 = (tid & 31) * 4;    // 4 keys per thread
    for (int j0 = 0; j0 < Lseq; j0 += 128) {
        const int cl = min(128, Lseq - j0);
        __syncthreads();
        for (int i = tid * 4; i < cl * 32; i += 1024) {
            int r = i >> 5, dd = i & 31;
            float4 gk = *(const float4*)(kptr + (size_t)(j0 + r) * 128 + dd);
            sKV[(dd + 0) * 132 + r] = gk.x;
            sKV[(dd + 1) * 132 + r] = gk.y;
            sKV[(dd + 2) * 132 + r] = gk.z;
            sKV[(dd + 3) * 132 + r] = gk.w;
        }
        __syncthreads();
        if (jj4 < cl) {
            float a00 = 0, a01 = 0, a02 = 0, a03 = 0;
            float a10 = 0, a11 = 0, a12 = 0, a13 = 0;
#pragma unroll
            for (int e = 0; e < 32; e++) {
                float q0 = sQ[(2 * qg) * 32 + e];
                float q1 = sQ[(2 * qg + 1) * 32 + e];
                float4 k4 = *(const float4*)(sKV + e * 132 + jj4);
                a00 = fmaf(q0, k4.x, a00); a01 = fmaf(q0, k4.y, a01);
                a02 = fmaf(q0, k4.z, a02); a03 = fmaf(q0, k4.w, a03);
                a10 = fmaf(q1, k4.x, a10); a11 = fmaf(q1, k4.y, a11);
                a12 = fmaf(q1, k4.z, a12); a13 = fmaf(q1, k4.w, a13);
            }
            float* r0 = sL + (2 * qg) * LPAD + j0 + jj4;
            float* r1 = r0 + LPAD;
            r0[0] = a00 * QSCALE; r0[1] = a01 * QSCALE; r0[2] = a02 * QSCALE; r0[3] = a03 * QSCALE;
            r1[0] = a10 * QSCALE; r1[1] = a11 * QSCALE; r1[2] = a12 * QSCALE; r1[3] = a13 * QSCALE;
        }
    }
    __syncthreads();

    // ---- softmax per row (warp w owns rows 2w, 2w+1) + write probs to gmem ----
    {
        const int w = tid >> 5, lane = tid & 31;
#pragma unroll
        for (int qq = 0; qq < 2; qq++) {
            const int q = w * 2 + qq;
            float* row = sL + q * LPAD;
            float m = -1e30f;
            for (int j = lane; j < Lseq; j += 32) m = fmaxf(m, row[j]);
#pragma unroll
            for (int o = 16; o; o >>= 1) m = fmaxf(m, __shfl_xor_sync(0xffffffffu, m, o));
            float s = 0.f;
            for (int j = lane; j < Lseq; j += 32) {
                float p = __expf(row[j] - m);
                row[j] = p; s += p;
            }
#pragma unroll
            for (int o = 16; o; o >>= 1) s += __shfl_xor_sync(0xffffffffu, s, o);
            const float inv = 1.0f / s;
            float* grow = P + (((size_t)b * Hh + hh) * Lseq + (l0 + q)) * (size_t)Lseq;
            for (int j = lane; j < Lseq; j += 32) {
                float p = row[j] * inv;
                row[j] = p;
                grow[j] = p;
            }
        }
    }

    // ---- O = P @ V, 128-key V chunks through SMEM, j-range split in halves ----
    const int half = tid >> 7;
    const int rem = tid & 127;
    const int q = rem >> 3;
    const int d4 = (rem & 7) * 4;
    float a0 = 0, a1 = 0, a2 = 0, a3 = 0;
    for (int j0 = 0; j0 < Lseq; j0 += 128) {
        const int cl = min(128, Lseq - j0);
        __syncthreads();
        for (int i = tid * 4; i < cl * 32; i += 1024) {
            int r = i >> 5, dd = i & 31;
            *(float4*)(sKV + r * 32 + dd) = *(const float4*)(vptr + (size_t)(j0 + r) * 128 + dd);
        }
        __syncthreads();
        const int cl2 = cl >> 1;
        const float* prow = sL + q * LPAD + j0 + half * cl2;
        const float* vv = sKV + half * cl2 * 32 + d4;
        for (int jj = 0; jj < cl2; jj++) {
            float p = prow[jj];
            float4 v4 = *(const float4*)(vv + jj * 32);
            a0 = fmaf(p, v4.x, a0); a1 = fmaf(p, v4.y, a1);
            a2 = fmaf(p, v4.z, a2); a3 = fmaf(p, v4.w, a3);
        }
    }
    __syncthreads();
    if (half) {
        float* sr = sQ + rem * 4;
        sr[0] = a0; sr[1] = a1; sr[2] = a2; sr[3] = a3;
    }
    __syncthreads();
    if (!half) {
        const float* sr = sQ + rem * 4;
        float4 o4 = make_float4(a0 + sr[0], a1 + sr[1], a2 + sr[2], a3 + sr[3]);
        *(float4*)(O + (size_t)(b * Lseq + l0 + q) * 128 + hh * 32 + d4) = o4;
    }
}

// ---------------------------------------------------------------------------
// Final head: out = t2 @ o2w + o2b   (N=2, K=256)
// ---------------------------------------------------------------------------
__global__ void head_kernel(const float* __restrict__ t2, const float* __restrict__ w,
                            const float* __restrict__ b, float* __restrict__ out) {
    int idx = blockIdx.x * 256 + threadIdx.x;
    if (idx >= MTOK * 2) return;
    int tok = idx >> 1, j = idx & 1;
    const float* a = t2 + (size_t)tok * 256;
    float acc = b[j];
#pragma unroll 8
    for (int k = 0; k < 256; k++) acc = fmaf(a[k], w[k * 2 + j], acc);
    out[idx] = acc;
}

// ---------------------------------------------------------------------------
// Driver
// ---------------------------------------------------------------------------
extern "C" void kernel_launch(void* const* d_in, const int* in_sizes, int n_in,
                              void* d_out, int out_size) {
    const float* x    = (const float*)d_in[0];
    const float* in_w = (const float*)d_in[1];
    const float* in_b = (const float*)d_in[2];
    const float* qw   = (const float*)d_in[3];
    const float* qb   = (const float*)d_in[4];
    const float* kw   = (const float*)d_in[5];
    const float* kb   = (const float*)d_in[6];
    const float* vw   = (const float*)d_in[7];
    const float* vb   = (const float*)d_in[8];
    const float* ow   = (const float*)d_in[9];
    const float* ob   = (const float*)d_in[10];
    const float* f1w  = (const float*)d_in[11];
    const float* f1b  = (const float*)d_in[12];
    const float* f2w  = (const float*)d_in[13];
    const float* f2b  = (const float*)d_in[14];
    const float* n1g  = (const float*)d_in[15];
    const float* n1b  = (const float*)d_in[16];
    const float* n2g  = (const float*)d_in[17];
    const float* n2b  = (const float*)d_in[18];
    const float* o1w  = (const float*)d_in[19];
    const float* o1b  = (const float*)d_in[20];
    const float* o2w  = (const float*)d_in[21];
    const float* o2b  = (const float*)d_in[22];
    float* out = (float*)d_out;

    float *h, *Qb, *Kb, *Vb, *Ob, *Tb, *Fb;
    cudaGetSymbolAddress((void**)&h,  g_h);
    cudaGetSymbolAddress((void**)&Qb, g_q);
    cudaGetSymbolAddress((void**)&Kb, g_k);
    cudaGetSymbolAddress((void**)&Vb, g_v);
    cudaGetSymbolAddress((void**)&Ob, g_o);
    cudaGetSymbolAddress((void**)&Tb, g_t);
    cudaGetSymbolAddress((void**)&Fb, g_f);

    const size_t smem_bytes = ATTN_SMEM_FLOATS * sizeof(float);
    cudaFuncSetAttribute(attn_kernel, cudaFuncAttributeMaxDynamicSharedMemorySize,
                         (int)smem_bytes);

    const int M = MTOK;
    inproj_kernel<<<(M * Dm + 255) / 256, 256>>>(x, in_w, in_b, h);

    const size_t ATTN_L = (size_t)8 * Hh * Lseq * Lseq;  // per-layer attns size
    for (int i = 0; i < 3; i++) {
        sgemm_kernel<<<dim3(M / 64, 2), 256>>>(h, qw + (size_t)i * 256 * 128, qb + i * 128, Qb, M, 128, 256, 0);
        sgemm_kernel<<<dim3(M / 64, 2), 256>>>(h, kw + (size_t)i * 256 * 128, kb + i * 128, Kb, M, 128, 256, 0);
        sgemm_kernel<<<dim3(M / 64, 2), 256>>>(h, vw + (size_t)i * 256 * 128, vb + i * 128, Vb, M, 128, 256, 0);

        attn_kernel<<<dim3(Lseq / 16, Hh, 8), 256, smem_bytes>>>(
            Qb, Kb, Vb, out + 32256 + (size_t)i * ATTN_L, Ob);

        sgemm_kernel<<<dim3(M / 64, 4), 256>>>(Ob, ow + (size_t)i * 128 * 256, ob + i * 256, Tb, M, 256, 128, 0);
        add_ln_kernel<<<M, 256>>>(h, Tb, n1g + i * 256, n1b + i * 256);

        sgemm_kernel<<<dim3(M / 64, 1), 256>>>(h, f1w + (size_t)i * 256 * 64, f1b + i * 64, Fb, M, 64, 256, 1);
        sgemm_kernel<<<dim3(M / 64, 4), 256>>>(Fb, f2w + (size_t)i * 64 * 256, f2b + i * 256, Tb, M, 256, 64, 0);
        add_ln_kernel<<<M, 256>>>(h, Tb, n2g + i * 256, n2b + i * 256);
    }

    sgemm_kernel<<<dim3(M / 64, 4), 256>>>(h, o1w, o1b, Tb, M, 256, 256, 1);
    head_kernel<<<(M * 2 + 255) / 256, 256>>>(Tb, o2w, o2b, out);
}

// round 4
// speedup vs baseline: 1.5909x; 1.5909x over previous
#include <cuda_runtime.h>
#include <cstdint>

// Problem constants
#define MTOK   16128          // B*L = 8*2016
#define Dm     256
#define Lseq   2016
#define Hh     4
#define QSCALE 0.0625f        // 1/sqrt(256)

// Attention tiling
#define CH     512            // key chunk
#define KSTR   516            // transposed K row stride (pad)
#define LPAD2  2052           // logit row stride (>= 2048, mult of 4)
// smem floats: sQt 512 | sKV 16512 | sL 16*2052=32832  -> 49856 floats
#define ATTN_SMEM_FLOATS (512 + 32 * KSTR + 16 * LPAD2)

// Scratch (static device globals; no allocation allowed)
__device__ float g_h[MTOK * Dm];
__device__ float g_q[MTOK * 128];
__device__ float g_k[MTOK * 128];
__device__ float g_v[MTOK * 128];
__device__ float g_o[MTOK * 128];
__device__ float g_t[MTOK * Dm];
__device__ float g_f[MTOK * 64];

// ---------------------------------------------------------------------------
// Input projection: h = x @ in_w + in_b   (K=2, trivial)
// ---------------------------------------------------------------------------
__global__ void inproj_kernel(const float* __restrict__ x, const float* __restrict__ w,
                              const float* __restrict__ b, float* __restrict__ h) {
    int idx = blockIdx.x * 256 + threadIdx.x;
    if (idx >= MTOK * Dm) return;
    int tok = idx >> 8, d = idx & 255;
    h[idx] = fmaf(x[2 * tok], w[d], fmaf(x[2 * tok + 1], w[256 + d], b[d]));
}

// ---------------------------------------------------------------------------
// SGEMM: C[M,N] = A[M,K] @ W[K,N] + bias (+relu). 128x64 tile, 256 thr, 8x4.
// M%128==0, N%64==0, K%16==0. blockIdx.z selects among 3 (W,bias,C) sets.
// ---------------------------------------------------------------------------
__global__ __launch_bounds__(256) void sgemm_kernel(
    const float* __restrict__ A,
    const float* __restrict__ W0, const float* __restrict__ W1, const float* __restrict__ W2,
    const float* __restrict__ bi0, const float* __restrict__ bi1, const float* __restrict__ bi2,
    float* __restrict__ C0, float* __restrict__ C1, float* __restrict__ C2,
    int M, int N, int K, int relu)
{
    const int z = blockIdx.z;
    const float* W    = (z == 0) ? W0  : (z == 1) ? W1  : W2;
    const float* bias = (z == 0) ? bi0 : (z == 1) ? bi1 : bi2;
    float*       C    = (z == 0) ? C0  : (z == 1) ? C1  : C2;

    __shared__ float As[16][132];   // [k][m]
    __shared__ float Ws[16][64];    // [k][n]
    const int t  = threadIdx.x;
    const int bm = blockIdx.x * 128, bn = blockIdx.y * 64;
    const int tx = t & 15, ty = t >> 4;            // n = tx*4, m = ty*8
    const int ar = t >> 1, ac = (t & 1) * 8;       // A load: row ar, k-offset ac (two f4)
    const int wr = t >> 4, wc = (t & 15) * 4;      // W load

    float acc[8][4];
#pragma unroll
    for (int i = 0; i < 8; i++)
#pragma unroll
        for (int j = 0; j < 4; j++) acc[i][j] = 0.f;

    for (int k0 = 0; k0 < K; k0 += 16) {
        float4 a0 = *(const float4*)(A + (size_t)(bm + ar) * K + k0 + ac);
        float4 a1 = *(const float4*)(A + (size_t)(bm + ar) * K + k0 + ac + 4);
        float4 wv = *(const float4*)(W + (size_t)(k0 + wr) * N + bn + wc);
        As[ac + 0][ar] = a0.x; As[ac + 1][ar] = a0.y;
        As[ac + 2][ar] = a0.z; As[ac + 3][ar] = a0.w;
        As[ac + 4][ar] = a1.x; As[ac + 5][ar] = a1.y;
        As[ac + 6][ar] = a1.z; As[ac + 7][ar] = a1.w;
        *(float4*)(&Ws[wr][wc]) = wv;
        __syncthreads();
#pragma unroll
        for (int k = 0; k < 16; k++) {
            float4 al = *(const float4*)(&As[k][ty * 8]);
            float4 ah = *(const float4*)(&As[k][ty * 8 + 4]);
            float4 w4 = *(const float4*)(&Ws[k][tx * 4]);
            float am[8] = {al.x, al.y, al.z, al.w, ah.x, ah.y, ah.z, ah.w};
#pragma unroll
            for (int i = 0; i < 8; i++) {
                acc[i][0] = fmaf(am[i], w4.x, acc[i][0]);
                acc[i][1] = fmaf(am[i], w4.y, acc[i][1]);
                acc[i][2] = fmaf(am[i], w4.z, acc[i][2]);
                acc[i][3] = fmaf(am[i], w4.w, acc[i][3]);
            }
        }
        __syncthreads();
    }
    float b0 = bias[bn + tx * 4 + 0], b1 = bias[bn + tx * 4 + 1];
    float b2 = bias[bn + tx * 4 + 2], b3 = bias[bn + tx * 4 + 3];
#pragma unroll
    for (int i = 0; i < 8; i++) {
        float4 o;
        o.x = acc[i][0] + b0; o.y = acc[i][1] + b1;
        o.z = acc[i][2] + b2; o.w = acc[i][3] + b3;
        if (relu) {
            o.x = fmaxf(o.x, 0.f); o.y = fmaxf(o.y, 0.f);
            o.z = fmaxf(o.z, 0.f); o.w = fmaxf(o.w, 0.f);
        }
        *(float4*)(C + (size_t)(bm + ty * 8 + i) * N + bn + tx * 4) = o;
    }
}

// ---------------------------------------------------------------------------
// Residual add + LayerNorm (D=256), one block per token, in-place into h
// ---------------------------------------------------------------------------
__global__ void add_ln_kernel(float* __restrict__ h, const float* __restrict__ t,
                              const float* __restrict__ g, const float* __restrict__ be) {
    __shared__ float red[8];
    const int row = blockIdx.x, i = threadIdx.x;
    const size_t base = (size_t)row * Dm;
    float v = h[base + i] + t[base + i];
    float s = v;
#pragma unroll
    for (int o = 16; o; o >>= 1) s += __shfl_xor_sync(0xffffffffu, s, o);
    if ((i & 31) == 0) red[i >> 5] = s;
    __syncthreads();
    float mean = 0.f;
#pragma unroll
    for (int k = 0; k < 8; k++) mean += red[k];
    mean *= (1.0f / Dm);
    __syncthreads();
    float d = v - mean;
    s = d * d;
#pragma unroll
    for (int o = 16; o; o >>= 1) s += __shfl_xor_sync(0xffffffffu, s, o);
    if ((i & 31) == 0) red[i >> 5] = s;
    __syncthreads();
    float var = 0.f;
#pragma unroll
    for (int k = 0; k < 8; k++) var += red[k];
    var *= (1.0f / Dm);
    h[base + i] = d * rsqrtf(var + 1e-5f) * g[i] + be[i];
}

// ---------------------------------------------------------------------------
// Attention: one CTA = (b, h, 16-query block), 512 threads (16 warps).
// Full 16 x Lseq logit rows in SMEM (stride LPAD2). Key chunks of 512,
// zero-padded so no tail guards are needed in compute loops.
// ---------------------------------------------------------------------------
__global__ __launch_bounds__(512) void attn_kernel(
    const float* __restrict__ Q, const float* __restrict__ K,
    const float* __restrict__ V, float* __restrict__ P, float* __restrict__ O)
{
    extern __shared__ float sm[];
    float* sQt = sm;                 // [32 e][16 q] transposed Q (reused as sR)
    float* sKV = sm + 512;           // K chunk transposed [32][KSTR] / V chunk [512][32]
    float* sL  = sm + 512 + 32 * KSTR;  // 16 rows, stride LPAD2

    const int tid  = threadIdx.x;
    const int warp = tid >> 5, lane = tid & 31;
    const int qb = blockIdx.x, hh = blockIdx.y, b = blockIdx.z;
    const int l0 = qb * 16;
    const float* qptr = Q + (size_t)b * Lseq * 128 + hh * 32;
    const float* kptr = K + (size_t)b * Lseq * 128 + hh * 32;
    const float* vptr = V + (size_t)b * Lseq * 128 + hh * 32;

    // ---- load Q transposed: sQt[d][q] ----
    {
        int r = tid >> 5, d = tid & 31;   // 16 x 32 = 512 threads exactly
        sQt[d * 16 + r] = qptr[(size_t)(l0 + r) * 128 + d];
    }

    // ---- logits: S = Q K^T * scale ----
    const int qg = warp & 3;      // 4 q rows: qg*4 ..
    const int kh = warp >> 2;     // 128-key block within the 512 chunk
    for (int j0 = 0; j0 < Lseq; j0 += CH) {
        __syncthreads();
        // load K chunk transposed (zero-padded past Lseq)
        for (int ii = tid; ii < (CH * 32) / 4; ii += 512) {
            int r = ii >> 3, d0 = (ii & 7) * 4;
            float4 kv = make_float4(0.f, 0.f, 0.f, 0.f);
            if (j0 + r < Lseq)
                kv = *(const float4*)(kptr + (size_t)(j0 + r) * 128 + d0);
            sKV[(d0 + 0) * KSTR + r] = kv.x;
            sKV[(d0 + 1) * KSTR + r] = kv.y;
            sKV[(d0 + 2) * KSTR + r] = kv.z;
            sKV[(d0 + 3) * KSTR + r] = kv.w;
        }
        __syncthreads();
        float acc[4][4];
#pragma unroll
        for (int i = 0; i < 4; i++)
#pragma unroll
            for (int j = 0; j < 4; j++) acc[i][j] = 0.f;
        const float* kbase = sKV + kh * 128 + lane * 4;
        const float* qbase = sQt + qg * 4;
#pragma unroll
        for (int e = 0; e < 32; e++) {
            float4 k4 = *(const float4*)(kbase + e * KSTR);
            float4 q4 = *(const float4*)(qbase + e * 16);
            acc[0][0] = fmaf(q4.x, k4.x, acc[0][0]); acc[0][1] = fmaf(q4.x, k4.y, acc[0][1]);
            acc[0][2] = fmaf(q4.x, k4.z, acc[0][2]); acc[0][3] = fmaf(q4.x, k4.w, acc[0][3]);
            acc[1][0] = fmaf(q4.y, k4.x, acc[1][0]); acc[1][1] = fmaf(q4.y, k4.y, acc[1][1]);
            acc[1][2] = fmaf(q4.y, k4.z, acc[1][2]); acc[1][3] = fmaf(q4.y, k4.w, acc[1][3]);
            acc[2][0] = fmaf(q4.z, k4.x, acc[2][0]); acc[2][1] = fmaf(q4.z, k4.y, acc[2][1]);
            acc[2][2] = fmaf(q4.z, k4.z, acc[2][2]); acc[2][3] = fmaf(q4.z, k4.w, acc[2][3]);
            acc[3][0] = fmaf(q4.w, k4.x, acc[3][0]); acc[3][1] = fmaf(q4.w, k4.y, acc[3][1]);
            acc[3][2] = fmaf(q4.w, k4.z, acc[3][2]); acc[3][3] = fmaf(q4.w, k4.w, acc[3][3]);
        }
        float* lrow = sL + (size_t)(qg * 4) * LPAD2 + j0 + kh * 128 + lane * 4;
#pragma unroll
        for (int r = 0; r < 4; r++) {
            float4 o = make_float4(acc[r][0] * QSCALE, acc[r][1] * QSCALE,
                                   acc[r][2] * QSCALE, acc[r][3] * QSCALE);
            *(float4*)(lrow + (size_t)r * LPAD2) = o;
        }
    }
    __syncthreads();

    // ---- softmax per row (warp w owns row w) + write probs to gmem ----
    {
        float* row = sL + (size_t)warp * LPAD2;
        float m = -1e30f;
        for (int j = lane; j < Lseq; j += 32) m = fmaxf(m, row[j]);
#pragma unroll
        for (int o = 16; o; o >>= 1) m = fmaxf(m, __shfl_xor_sync(0xffffffffu, m, o));
        float s = 0.f;
        for (int j = lane; j < Lseq; j += 32) {
            float p = __expf(row[j] - m);
            row[j] = p; s += p;
        }
#pragma unroll
        for (int o = 16; o; o >>= 1) s += __shfl_xor_sync(0xffffffffu, s, o);
        const float inv = 1.0f / s;
        float* grow = P + (((size_t)b * Hh + hh) * Lseq + (l0 + warp)) * (size_t)Lseq;
        for (int j = lane; j < Lseq; j += 32) {
            float p = row[j] * inv;
            row[j] = p;
            grow[j] = p;
        }
    }

    // ---- O = P @ V ----
    const int qp = warp & 7;        // rows 2qp, 2qp+1
    const int jh = warp >> 3;       // 256-key half of the 512 chunk
    const int jq = lane >> 3;       // j stagger 0..3
    const int d4 = (lane & 7) * 4;  // 4 of 32 dims
    float o0[4] = {0.f, 0.f, 0.f, 0.f}, o1[4] = {0.f, 0.f, 0.f, 0.f};
    for (int j0 = 0; j0 < Lseq; j0 += CH) {
        __syncthreads();
        for (int ii = tid; ii < (CH * 32) / 4; ii += 512) {
            int r = ii >> 3, d0 = (ii & 7) * 4;
            float4 v = make_float4(0.f, 0.f, 0.f, 0.f);
            if (j0 + r < Lseq)
                v = *(const float4*)(vptr + (size_t)(j0 + r) * 128 + d0);
            *(float4*)(sKV + r * 32 + d0) = v;
        }
        __syncthreads();
        const float* p0 = sL + (size_t)(2 * qp) * LPAD2 + j0 + jh * 256 + jq;
        const float* p1 = p0 + LPAD2;
        const float* vb = sKV + (jh * 256 + jq) * 32 + d4;
#pragma unroll 8
        for (int i = 0; i < 64; i++) {
            float a = p0[i * 4];
            float c = p1[i * 4];
            float4 v4 = *(const float4*)(vb + i * 128);
            o0[0] = fmaf(a, v4.x, o0[0]); o0[1] = fmaf(a, v4.y, o0[1]);
            o0[2] = fmaf(a, v4.z, o0[2]); o0[3] = fmaf(a, v4.w, o0[3]);
            o1[0] = fmaf(c, v4.x, o1[0]); o1[1] = fmaf(c, v4.y, o1[1]);
            o1[2] = fmaf(c, v4.z, o1[2]); o1[3] = fmaf(c, v4.w, o1[3]);
        }
    }
    // reduce across jq groups (lanes xor 8, 16)
#pragma unroll
    for (int s = 0; s < 4; s++) {
        o0[s] += __shfl_xor_sync(0xffffffffu, o0[s], 8);
        o0[s] += __shfl_xor_sync(0xffffffffu, o0[s], 16);
        o1[s] += __shfl_xor_sync(0xffffffffu, o1[s], 8);
        o1[s] += __shfl_xor_sync(0xffffffffu, o1[s], 16);
    }
    float* sR = sQt;   // 16 x 32 reduction scratch (sQt no longer needed)
    __syncthreads();
    if (jh == 1 && lane < 8) {
#pragma unroll
        for (int s = 0; s < 4; s++) {
            sR[(2 * qp + 0) * 32 + d4 + s] = o0[s];
            sR[(2 * qp + 1) * 32 + d4 + s] = o1[s];
        }
    }
    __syncthreads();
    if (jh == 0 && lane < 8) {
        float4 r0 = make_float4(o0[0] + sR[(2 * qp + 0) * 32 + d4 + 0],
                                o0[1] + sR[(2 * qp + 0) * 32 + d4 + 1],
                                o0[2] + sR[(2 * qp + 0) * 32 + d4 + 2],
                                o0[3] + sR[(2 * qp + 0) * 32 + d4 + 3]);
        float4 r1 = make_float4(o1[0] + sR[(2 * qp + 1) * 32 + d4 + 0],
                                o1[1] + sR[(2 * qp + 1) * 32 + d4 + 1],
                                o1[2] + sR[(2 * qp + 1) * 32 + d4 + 2],
                                o1[3] + sR[(2 * qp + 1) * 32 + d4 + 3]);
        *(float4*)(O + (size_t)(b * Lseq + l0 + 2 * qp + 0) * 128 + hh * 32 + d4) = r0;
        *(float4*)(O + (size_t)(b * Lseq + l0 + 2 * qp + 1) * 128 + hh * 32 + d4) = r1;
    }
}

// ---------------------------------------------------------------------------
// Final head: out = t2 @ o2w + o2b   (N=2, K=256)
// ---------------------------------------------------------------------------
__global__ void head_kernel(const float* __restrict__ t2, const float* __restrict__ w,
                            const float* __restrict__ b, float* __restrict__ out) {
    int idx = blockIdx.x * 256 + threadIdx.x;
    if (idx >= MTOK * 2) return;
    int tok = idx >> 1, j = idx & 1;
    const float* a = t2 + (size_t)tok * 256;
    float acc = b[j];
#pragma unroll 8
    for (int k = 0; k < 256; k++) acc = fmaf(a[k], w[k * 2 + j], acc);
    out[idx] = acc;
}

// ---------------------------------------------------------------------------
// Driver
// ---------------------------------------------------------------------------
extern "C" void kernel_launch(void* const* d_in, const int* in_sizes, int n_in,
                              void* d_out, int out_size) {
    const float* x    = (const float*)d_in[0];
    const float* in_w = (const float*)d_in[1];
    const float* in_b = (const float*)d_in[2];
    const float* qw   = (const float*)d_in[3];
    const float* qb   = (const float*)d_in[4];
    const float* kw   = (const float*)d_in[5];
    const float* kb   = (const float*)d_in[6];
    const float* vw   = (const float*)d_in[7];
    const float* vb   = (const float*)d_in[8];
    const float* ow   = (const float*)d_in[9];
    const float* ob   = (const float*)d_in[10];
    const float* f1w  = (const float*)d_in[11];
    const float* f1b  = (const float*)d_in[12];
    const float* f2w  = (const float*)d_in[13];
    const float* f2b  = (const float*)d_in[14];
    const float* n1g  = (const float*)d_in[15];
    const float* n1b  = (const float*)d_in[16];
    const float* n2g  = (const float*)d_in[17];
    const float* n2b  = (const float*)d_in[18];
    const float* o1w  = (const float*)d_in[19];
    const float* o1b  = (const float*)d_in[20];
    const float* o2w  = (const float*)d_in[21];
    const float* o2b  = (const float*)d_in[22];
    float* out = (float*)d_out;

    float *h, *Qb, *Kb, *Vb, *Ob, *Tb, *Fb;
    cudaGetSymbolAddress((void**)&h,  g_h);
    cudaGetSymbolAddress((void**)&Qb, g_q);
    cudaGetSymbolAddress((void**)&Kb, g_k);
    cudaGetSymbolAddress((void**)&Vb, g_v);
    cudaGetSymbolAddress((void**)&Ob, g_o);
    cudaGetSymbolAddress((void**)&Tb, g_t);
    cudaGetSymbolAddress((void**)&Fb, g_f);

    const size_t smem_bytes = ATTN_SMEM_FLOATS * sizeof(float);
    cudaFuncSetAttribute(attn_kernel, cudaFuncAttributeMaxDynamicSharedMemorySize,
                         (int)smem_bytes);

    const int M = MTOK;
    inproj_kernel<<<(M * Dm + 255) / 256, 256>>>(x, in_w, in_b, h);

    const size_t ATTN_L = (size_t)8 * Hh * Lseq * Lseq;  // per-layer attns size
    for (int i = 0; i < 3; i++) {
        const float* qwi = qw + (size_t)i * 256 * 128;
        const float* kwi = kw + (size_t)i * 256 * 128;
        const float* vwi = vw + (size_t)i * 256 * 128;
        // fused QKV: grid z selects q/k/v
        sgemm_kernel<<<dim3(M / 128, 2, 3), 256>>>(
            h, qwi, kwi, vwi, qb + i * 128, kb + i * 128, vb + i * 128,
            Qb, Kb, Vb, M, 128, 256, 0);

        attn_kernel<<<dim3(Lseq / 16, Hh, 8), 512, smem_bytes>>>(
            Qb, Kb, Vb, out + 32256 + (size_t)i * ATTN_L, Ob);

        const float* owi = ow + (size_t)i * 128 * 256;
        sgemm_kernel<<<dim3(M / 128, 4, 1), 256>>>(
            Ob, owi, owi, owi, ob + i * 256, ob + i * 256, ob + i * 256,
            Tb, Tb, Tb, M, 256, 128, 0);
        add_ln_kernel<<<M, 256>>>(h, Tb, n1g + i * 256, n1b + i * 256);

        const float* f1wi = f1w + (size_t)i * 256 * 64;
        sgemm_kernel<<<dim3(M / 128, 1, 1), 256>>>(
            h, f1wi, f1wi, f1wi, f1b + i * 64, f1b + i * 64, f1b + i * 64,
            Fb, Fb, Fb, M, 64, 256, 1);
        const float* f2wi = f2w + (size_t)i * 64 * 256;
        sgemm_kernel<<<dim3(M / 128, 4, 1), 256>>>(
            Fb, f2wi, f2wi, f2wi, f2b + i * 256, f2b + i * 256, f2b + i * 256,
            Tb, Tb, Tb, M, 256, 64, 0);
        add_ln_kernel<<<M, 256>>>(h, Tb, n2g + i * 256, n2b + i * 256);
    }

    sgemm_kernel<<<dim3(M / 128, 4, 1), 256>>>(
        h, o1w, o1w, o1w, o1b, o1b, o1b, Tb, Tb, Tb, M, 256, 256, 1);
    head_kernel<<<(M * 2 + 255) / 256, 256>>>(Tb, o2w, o2b, out);
}

// round 7
// speedup vs baseline: 2.1273x; 1.3371x over previous
#include <cuda_runtime.h>
#include <cstdint>

// Problem constants
#define MTOK   16128          // B*L = 8*2016
#define Dm     256
#define Lseq   2016
#define Hh     4
#define QSCALE 0.0625f        // 1/sqrt(256)

// Attention tiling
#define CH     512            // key chunk
#define LPAD2  2052           // logit row stride (>= 2048, mult of 4)
// smem floats: sQ 512 | sKV 16384 | sL 16*2052 | sInv 16
#define ATTN_SMEM_FLOATS (512 + 16384 + 16 * LPAD2 + 16)

// Scratch (static device globals; no allocation allowed)
__device__ float g_h[MTOK * Dm];
__device__ float g_q[MTOK * 128];
__device__ float g_k[MTOK * 128];
__device__ float g_v[MTOK * 128];
__device__ float g_o[MTOK * 128];
__device__ float g_t[MTOK * Dm];
__device__ float g_f[MTOK * 64];

// packed fp32x2 FMA (Blackwell): d = a*b + d elementwise on 2 floats
#define FMA2(acc, a, b) \
    asm("fma.rn.f32x2 %0, %1, %2, %0;" : "+l"(acc) : "l"(a), "l"(b))

static __device__ __forceinline__ float ull_lo(unsigned long long v) {
    return __uint_as_float((unsigned int)v);
}
static __device__ __forceinline__ float ull_hi(unsigned long long v) {
    return __uint_as_float((unsigned int)(v >> 32));
}

// ---------------------------------------------------------------------------
// Input projection: h = x @ in_w + in_b   (K=2, trivial)
// ---------------------------------------------------------------------------
__global__ void inproj_kernel(const float* __restrict__ x, const float* __restrict__ w,
                              const float* __restrict__ b, float* __restrict__ h) {
    int idx = blockIdx.x * 256 + threadIdx.x;
    if (idx >= MTOK * Dm) return;
    int tok = idx >> 8, d = idx & 255;
    h[idx] = fmaf(x[2 * tok], w[d], fmaf(x[2 * tok + 1], w[256 + d], b[d]));
}

// ---------------------------------------------------------------------------
// SGEMM: C[M,N] = A[M,K] @ W[K,N] + bias (+relu). 128x64 tile, 256 thr, 8x4.
// M%128==0, N%64==0, K%16==0. blockIdx.z selects among 3 (W,bias,C) sets.
// ---------------------------------------------------------------------------
__global__ __launch_bounds__(256) void sgemm_kernel(
    const float* __restrict__ A,
    const float* __restrict__ W0, const float* __restrict__ W1, const float* __restrict__ W2,
    const float* __restrict__ bi0, const float* __restrict__ bi1, const float* __restrict__ bi2,
    float* __restrict__ C0, float* __restrict__ C1, float* __restrict__ C2,
    int M, int N, int K, int relu)
{
    const int z = blockIdx.z;
    const float* W    = (z == 0) ? W0  : (z == 1) ? W1  : W2;
    const float* bias = (z == 0) ? bi0 : (z == 1) ? bi1 : bi2;
    float*       C    = (z == 0) ? C0  : (z == 1) ? C1  : C2;

    __shared__ float As[16][132];   // [k][m]
    __shared__ float Ws[16][64];    // [k][n]
    const int t  = threadIdx.x;
    const int bm = blockIdx.x * 128, bn = blockIdx.y * 64;
    const int tx = t & 15, ty = t >> 4;            // n = tx*4, m = ty*8
    const int ar = t >> 1, ac = (t & 1) * 8;       // A load: row ar, k-offset ac
    const int wr = t >> 4, wc = (t & 15) * 4;      // W load

    float acc[8][4];
#pragma unroll
    for (int i = 0; i < 8; i++)
#pragma unroll
        for (int j = 0; j < 4; j++) acc[i][j] = 0.f;

    for (int k0 = 0; k0 < K; k0 += 16) {
        float4 a0 = *(const float4*)(A + (size_t)(bm + ar) * K + k0 + ac);
        float4 a1 = *(const float4*)(A + (size_t)(bm + ar) * K + k0 + ac + 4);
        float4 wv = *(const float4*)(W + (size_t)(k0 + wr) * N + bn + wc);
        As[ac + 0][ar] = a0.x; As[ac + 1][ar] = a0.y;
        As[ac + 2][ar] = a0.z; As[ac + 3][ar] = a0.w;
        As[ac + 4][ar] = a1.x; As[ac + 5][ar] = a1.y;
        As[ac + 6][ar] = a1.z; As[ac + 7][ar] = a1.w;
        *(float4*)(&Ws[wr][wc]) = wv;
        __syncthreads();
#pragma unroll
        for (int k = 0; k < 16; k++) {
            float4 al = *(const float4*)(&As[k][ty * 8]);
            float4 ah = *(const float4*)(&As[k][ty * 8 + 4]);
            float4 w4 = *(const float4*)(&Ws[k][tx * 4]);
            float am[8] = {al.x, al.y, al.z, al.w, ah.x, ah.y, ah.z, ah.w};
#pragma unroll
            for (int i = 0; i < 8; i++) {
                acc[i][0] = fmaf(am[i], w4.x, acc[i][0]);
                acc[i][1] = fmaf(am[i], w4.y, acc[i][1]);
                acc[i][2] = fmaf(am[i], w4.z, acc[i][2]);
                acc[i][3] = fmaf(am[i], w4.w, acc[i][3]);
            }
        }
        __syncthreads();
    }
    float b0 = bias[bn + tx * 4 + 0], b1 = bias[bn + tx * 4 + 1];
    float b2 = bias[bn + tx * 4 + 2], b3 = bias[bn + tx * 4 + 3];
#pragma unroll
    for (int i = 0; i < 8; i++) {
        float4 o;
        o.x = acc[i][0] + b0; o.y = acc[i][1] + b1;
        o.z = acc[i][2] + b2; o.w = acc[i][3] + b3;
        if (relu) {
            o.x = fmaxf(o.x, 0.f); o.y = fmaxf(o.y, 0.f);
            o.z = fmaxf(o.z, 0.f); o.w = fmaxf(o.w, 0.f);
        }
        *(float4*)(C + (size_t)(bm + ty * 8 + i) * N + bn + tx * 4) = o;
    }
}

// ---------------------------------------------------------------------------
// Residual add + LayerNorm (D=256), one block per token, in-place into h
// ---------------------------------------------------------------------------
__global__ void add_ln_kernel(float* __restrict__ h, const float* __restrict__ t,
                              const float* __restrict__ g, const float* __restrict__ be) {
    __shared__ float red[8];
    const int row = blockIdx.x, i = threadIdx.x;
    const size_t base = (size_t)row * Dm;
    float v = h[base + i] + t[base + i];
    float s = v;
#pragma unroll
    for (int o = 16; o; o >>= 1) s += __shfl_xor_sync(0xffffffffu, s, o);
    if ((i & 31) == 0) red[i >> 5] = s;
    __syncthreads();
    float mean = 0.f;
#pragma unroll
    for (int k = 0; k < 8; k++) mean += red[k];
    mean *= (1.0f / Dm);
    __syncthreads();
    float d = v - mean;
    s = d * d;
#pragma unroll
    for (int o = 16; o; o >>= 1) s += __shfl_xor_sync(0xffffffffu, s, o);
    if ((i & 31) == 0) red[i >> 5] = s;
    __syncthreads();
    float var = 0.f;
#pragma unroll
    for (int k = 0; k < 8; k++) var += red[k];
    var *= (1.0f / Dm);
    h[base + i] = d * rsqrtf(var + 1e-5f) * g[i] + be[i];
}

// ---------------------------------------------------------------------------
// Attention: one CTA = (b, h, 16-query block), 512 threads (16 warps).
// Full 16 x Lseq logit rows in SMEM (stride LPAD2). Key chunks of 512,
// zero-padded. FFMA2 (f32x2) with naturally-paired operands everywhere:
//   logits: pair along e  (Q [q][e], K [j][e] XOR-swizzled rows)
//   PV:     pair along j  (P rows, V transposed [d][j] XOR-swizzled)
// ---------------------------------------------------------------------------
__global__ __launch_bounds__(512) void attn_kernel(
    const float* __restrict__ Q, const float* __restrict__ K,
    const float* __restrict__ V, float* __restrict__ P, float* __restrict__ O)
{
    extern __shared__ float sm[];
    float* sQ   = sm;                  // [16 q][32 e]
    float* sKV  = sm + 512;            // K [512][32] swizzled / V [32][512] swizzled
    float* sL   = sm + 512 + 16384;    // 16 rows, stride LPAD2 (probs, unnormalized)
    float* sInv = sL + 16 * LPAD2;     // [16] 1/rowsum

    const int tid  = threadIdx.x;
    const int warp = tid >> 5, lane = tid & 31;
    const int qb = blockIdx.x, hh = blockIdx.y, b = blockIdx.z;
    const int l0 = qb * 16;
    const float* qptr = Q + (size_t)b * Lseq * 128 + hh * 32;
    const float* kptr = K + (size_t)b * Lseq * 128 + hh * 32;
    const float* vptr = V + (size_t)b * Lseq * 128 + hh * 32;

    // ---- load Q natural [q][e] (512 threads exactly) ----
    sQ[tid] = qptr[(size_t)(l0 + warp) * 128 + lane];

    // ---- logits: S = Q K^T * scale (e-paired FFMA2) ----
    {
        const int qg = warp & 3;       // q rows qg*4 .. qg*4+3
        const int kh = warp >> 2;      // 128-j block within chunk
        const int jbase = kh * 128 + lane;
        for (int j0 = 0; j0 < Lseq; j0 += CH) {
            __syncthreads();
            // load K chunk: row r holds e0..31, float4 groups XOR-swizzled by r&7
#pragma unroll
            for (int s = 0; s < 8; s++) {
                int ii = tid + s * 512;
                int r = ii >> 3, e4 = ii & 7;
                float4 kv = make_float4(0.f, 0.f, 0.f, 0.f);
                if (j0 + r < Lseq)
                    kv = *(const float4*)(kptr + (size_t)(j0 + r) * 128 + e4 * 4);
                *(float4*)(sKV + r * 32 + ((e4 ^ (r & 7)) << 2)) = kv;
            }
            __syncthreads();
            unsigned long long acc[4][4];
#pragma unroll
            for (int qq = 0; qq < 4; qq++)
#pragma unroll
                for (int c = 0; c < 4; c++) acc[qq][c] = 0ULL;
#pragma unroll
            for (int e4 = 0; e4 < 8; e4++) {
                ulonglong2 qp[4];
#pragma unroll
                for (int qq = 0; qq < 4; qq++)
                    qp[qq] = *(const ulonglong2*)(sQ + (qg * 4 + qq) * 32 + e4 * 4);
#pragma unroll
                for (int c = 0; c < 4; c++) {
                    const int j = jbase + 32 * c;
                    ulonglong2 kp = *(const ulonglong2*)(sKV + j * 32 + ((e4 ^ (j & 7)) << 2));
#pragma unroll
                    for (int qq = 0; qq < 4; qq++) {
                        FMA2(acc[qq][c], qp[qq].x, kp.x);
                        FMA2(acc[qq][c], qp[qq].y, kp.y);
                    }
                }
            }
#pragma unroll
            for (int qq = 0; qq < 4; qq++)
#pragma unroll
                for (int c = 0; c < 4; c++) {
                    float s = (ull_lo(acc[qq][c]) + ull_hi(acc[qq][c])) * QSCALE;
                    sL[(size_t)(qg * 4 + qq) * LPAD2 + j0 + jbase + 32 * c] = s;
                }
        }
    }
    __syncthreads();

    // ---- softmax per row (warp w owns row w); keep UNNORMALIZED p in smem ----
    {
        float* row = sL + (size_t)warp * LPAD2;
        float m = -1e30f;
        for (int j = lane; j < Lseq; j += 32) m = fmaxf(m, row[j]);
#pragma unroll
        for (int o = 16; o; o >>= 1) m = fmaxf(m, __shfl_xor_sync(0xffffffffu, m, o));
        float s = 0.f;
        for (int j = lane; j < Lseq; j += 32) {
            float p = __expf(row[j] - m);
            row[j] = p; s += p;
        }
#pragma unroll
        for (int o = 16; o; o >>= 1) s += __shfl_xor_sync(0xffffffffu, s, o);
        const float inv = 1.0f / s;
        if (lane == 0) sInv[warp] = inv;
        float* grow = P + (((size_t)b * Hh + hh) * Lseq + (l0 + warp)) * (size_t)Lseq;
        for (int j = lane; j < Lseq; j += 32) grow[j] = row[j] * inv;
    }

    // ---- O = P @ V (j-paired FFMA2, V transposed [d][j] swizzled) ----
    const int qg2 = warp >> 2;        // q rows qg2*4 .. +3
    const int jh  = warp & 3;         // 128-j block within chunk
    const int m8  = lane & 7;         // d group: d = m8*4 + cc
    const int jq  = lane >> 3;        // j stagger 0..3
    unsigned long long acc[4][4];
#pragma unroll
    for (int qq = 0; qq < 4; qq++)
#pragma unroll
        for (int cc = 0; cc < 4; cc++) acc[qq][cc] = 0ULL;

    for (int j0 = 0; j0 < Lseq; j0 += CH) {
        __syncthreads();
        // load V chunk transposed: element (d, j) at d*512 + ((j>>2 ^ (d>>2&7))*4 + (j&3))
#pragma unroll
        for (int s = 0; s < 8; s++) {
            int ii = tid + s * 512;
            int r = ii >> 3, dg = ii & 7;
            float4 v = make_float4(0.f, 0.f, 0.f, 0.f);
            if (j0 + r < Lseq)
                v = *(const float4*)(vptr + (size_t)(j0 + r) * 128 + dg * 4);
            int r4 = r >> 2, rl = r & 3;
            int swb = ((r4 ^ dg) << 2) + rl;
            sKV[(dg * 4 + 0) * 512 + swb] = v.x;
            sKV[(dg * 4 + 1) * 512 + swb] = v.y;
            sKV[(dg * 4 + 2) * 512 + swb] = v.z;
            sKV[(dg * 4 + 3) * 512 + swb] = v.w;
        }
        __syncthreads();
#pragma unroll
        for (int i = 0; i < 8; i++) {
            const int j = jh * 128 + i * 16 + jq * 4;
            const int j4 = j >> 2;
            ulonglong2 pp[4];
#pragma unroll
            for (int qq = 0; qq < 4; qq++)
                pp[qq] = *(const ulonglong2*)(sL + (size_t)(qg2 * 4 + qq) * LPAD2 + j0 + j);
#pragma unroll
            for (int cc = 0; cc < 4; cc++) {
                const int d = m8 * 4 + cc;
                ulonglong2 vp = *(const ulonglong2*)(sKV + d * 512 + ((j4 ^ m8) << 2));
#pragma unroll
                for (int qq = 0; qq < 4; qq++) {
                    FMA2(acc[qq][cc], pp[qq].x, vp.x);
                    FMA2(acc[qq][cc], pp[qq].y, vp.y);
                }
            }
        }
    }
    // horizontal (even/odd j halves) + reduce across jq via shuffles
    float part[4][4];
#pragma unroll
    for (int qq = 0; qq < 4; qq++)
#pragma unroll
        for (int cc = 0; cc < 4; cc++) {
            float p = ull_lo(acc[qq][cc]) + ull_hi(acc[qq][cc]);
            p += __shfl_xor_sync(0xffffffffu, p, 8);
            p += __shfl_xor_sync(0xffffffffu, p, 16);
            part[qq][cc] = p;
        }
    __syncthreads();   // done reading sKV (V) and sL
    if (jq == 0) {     // lanes 0..7 hold jq-reduced partials; write per-jh partials
#pragma unroll
        for (int qq = 0; qq < 4; qq++)
#pragma unroll
            for (int cc = 0; cc < 4; cc++)
                sKV[jh * 512 + (qg2 * 4 + qq) * 32 + m8 * 4 + cc] = part[qq][cc];
    }
    __syncthreads();
    {
        const int q = warp;        // 16 warps -> 16 q rows, d = lane
        float o = sKV[0 * 512 + q * 32 + lane] + sKV[1 * 512 + q * 32 + lane] +
                  sKV[2 * 512 + q * 32 + lane] + sKV[3 * 512 + q * 32 + lane];
        o *= sInv[q];
        O[(size_t)(b * Lseq + l0 + q) * 128 + hh * 32 + lane] = o;
    }
}

// ---------------------------------------------------------------------------
// Final head: out = t2 @ o2w + o2b   (N=2, K=256)
// ---------------------------------------------------------------------------
__global__ void head_kernel(const float* __restrict__ t2, const float* __restrict__ w,
                            const float* __restrict__ b, float* __restrict__ out) {
    int idx = blockIdx.x * 256 + threadIdx.x;
    if (idx >= MTOK * 2) return;
    int tok = idx >> 1, j = idx & 1;
    const float* a = t2 + (size_t)tok * 256;
    float acc = b[j];
#pragma unroll 8
    for (int k = 0; k < 256; k++) acc = fmaf(a[k], w[k * 2 + j], acc);
    out[idx] = acc;
}

// ---------------------------------------------------------------------------
// Driver
// ---------------------------------------------------------------------------
extern "C" void kernel_launch(void* const* d_in, const int* in_sizes, int n_in,
                              void* d_out, int out_size) {
    const float* x    = (const float*)d_in[0];
    const float* in_w = (const float*)d_in[1];
    const float* in_b = (const float*)d_in[2];
    const float* qw   = (const float*)d_in[3];
    const float* qb   = (const float*)d_in[4];
    const float* kw   = (const float*)d_in[5];
    const float* kb   = (const float*)d_in[6];
    const float* vw   = (const float*)d_in[7];
    const float* vb   = (const float*)d_in[8];
    const float* ow   = (const float*)d_in[9];
    const float* ob   = (const float*)d_in[10];
    const float* f1w  = (const float*)d_in[11];
    const float* f1b  = (const float*)d_in[12];
    const float* f2w  = (const float*)d_in[13];
    const float* f2b  = (const float*)d_in[14];
    const float* n1g  = (const float*)d_in[15];
    const float* n1b  = (const float*)d_in[16];
    const float* n2g  = (const float*)d_in[17];
    const float* n2b  = (const float*)d_in[18];
    const float* o1w  = (const float*)d_in[19];
    const float* o1b  = (const float*)d_in[20];
    const float* o2w  = (const float*)d_in[21];
    const float* o2b  = (const float*)d_in[22];
    float* out = (float*)d_out;

    float *h, *Qb, *Kb, *Vb, *Ob, *Tb, *Fb;
    cudaGetSymbolAddress((void**)&h,  g_h);
    cudaGetSymbolAddress((void**)&Qb, g_q);
    cudaGetSymbolAddress((void**)&Kb, g_k);
    cudaGetSymbolAddress((void**)&Vb, g_v);
    cudaGetSymbolAddress((void**)&Ob, g_o);
    cudaGetSymbolAddress((void**)&Tb, g_t);
    cudaGetSymbolAddress((void**)&Fb, g_f);

    const size_t smem_bytes = ATTN_SMEM_FLOATS * sizeof(float);
    cudaFuncSetAttribute(attn_kernel, cudaFuncAttributeMaxDynamicSharedMemorySize,
                         (int)smem_bytes);

    const int M = MTOK;
    inproj_kernel<<<(M * Dm + 255) / 256, 256>>>(x, in_w, in_b, h);

    const size_t ATTN_L = (size_t)8 * Hh * Lseq * Lseq;  // per-layer attns size
    for (int i = 0; i < 3; i++) {
        const float* qwi = qw + (size_t)i * 256 * 128;
        const float* kwi = kw + (size_t)i * 256 * 128;
        const float* vwi = vw + (size_t)i * 256 * 128;
        sgemm_kernel<<<dim3(M / 128, 2, 3), 256>>>(
            h, qwi, kwi, vwi, qb + i * 128, kb + i * 128, vb + i * 128,
            Qb, Kb, Vb, M, 128, 256, 0);

        attn_kernel<<<dim3(Lseq / 16, Hh, 8), 512, smem_bytes>>>(
            Qb, Kb, Vb, out + 32256 + (size_t)i * ATTN_L, Ob);

        const float* owi = ow + (size_t)i * 128 * 256;
        sgemm_kernel<<<dim3(M / 128, 4, 1), 256>>>(
            Ob, owi, owi, owi, ob + i * 256, ob + i * 256, ob + i * 256,
            Tb, Tb, Tb, M, 256, 128, 0);
        add_ln_kernel<<<M, 256>>>(h, Tb, n1g + i * 256, n1b + i * 256);

        const float* f1wi = f1w + (size_t)i * 256 * 64;
        sgemm_kernel<<<dim3(M / 128, 1, 1), 256>>>(
            h, f1wi, f1wi, f1wi, f1b + i * 64, f1b + i * 64, f1b + i * 64,
            Fb, Fb, Fb, M, 64, 256, 1);
        const float* f2wi = f2w + (size_t)i * 64 * 256;
        sgemm_kernel<<<dim3(M / 128, 4, 1), 256>>>(
            Fb, f2wi, f2wi, f2wi, f2b + i * 256, f2b + i * 256, f2b + i * 256,
            Tb, Tb, Tb, M, 256, 64, 0);
        add_ln_kernel<<<M, 256>>>(h, Tb, n2g + i * 256, n2b + i * 256);
    }

    sgemm_kernel<<<dim3(M / 128, 4, 1), 256>>>(
        h, o1w, o1w, o1w, o1b, o1b, o1b, Tb, Tb, Tb, M, 256, 256, 1);
    head_kernel<<<(M * 2 + 255) / 256, 256>>>(Tb, o2w, o2b, out);
}

// round 11
// speedup vs baseline: 2.1927x; 1.0307x over previous
#include <cuda_runtime.h>
#include <cstdint>

// Problem constants
#define MTOK   16128          // B*L = 8*2016
#define Dm     256
#define Lseq   2016
#define Hh     4
#define QSCALE 0.0625f        // 1/sqrt(256)

// Attention tiling
#define CH     512            // key chunk
#define LPAD2  2052           // logit row stride (>= 2048, mult of 4)
// smem floats: sQ 512 | sKV 16384 | sL 16*2052 | sInv 16
#define ATTN_SMEM_FLOATS (512 + 16384 + 16 * LPAD2 + 16)

// Scratch (static device globals; no allocation allowed)
__device__ float g_h[MTOK * Dm];
__device__ float g_q[MTOK * 128];
__device__ float g_k[MTOK * 128];
__device__ float g_v[MTOK * 128];
__device__ float g_o[MTOK * 128];
__device__ float g_t[MTOK * Dm];
__device__ float g_f[MTOK * 64];

// packed fp32x2 FMA (Blackwell): d = a*b + d elementwise on 2 floats
#define FMA2(acc, a, b) \
    asm("fma.rn.f32x2 %0, %1, %2, %0;" : "+l"(acc) : "l"(a), "l"(b))

// duplicate one fp32 into both halves of an f32x2 register
#define PACK2(out, v) \
    asm("mov.b64 %0, {%1, %1};" : "=l"(out) : "r"(__float_as_uint(v)))

static __device__ __forceinline__ float ull_lo(unsigned long long v) {
    return __uint_as_float((unsigned int)v);
}
static __device__ __forceinline__ float ull_hi(unsigned long long v) {
    return __uint_as_float((unsigned int)(v >> 32));
}

// ---------------------------------------------------------------------------
// Input projection: h = x @ in_w + in_b   (K=2, trivial)
// ---------------------------------------------------------------------------
__global__ void inproj_kernel(const float* __restrict__ x, const float* __restrict__ w,
                              const float* __restrict__ b, float* __restrict__ h) {
    int idx = blockIdx.x * 256 + threadIdx.x;
    if (idx >= MTOK * Dm) return;
    int tok = idx >> 8, d = idx & 255;
    h[idx] = fmaf(x[2 * tok], w[d], fmaf(x[2 * tok + 1], w[256 + d], b[d]));
}

// ---------------------------------------------------------------------------
// SGEMM: C[M,N] = A[M,K] @ W[K,N] + bias (+relu). 128x64 tile, 256 thr.
// FFMA2 microtile: 4 m-pairs x 4 n. As[k][m] gives natural m-pairs; W packed.
// M%128==0, N%64==0, K%16==0. blockIdx.z selects among 3 (W,bias,C) sets.
// ---------------------------------------------------------------------------
__global__ __launch_bounds__(256) void sgemm_kernel(
    const float* __restrict__ A,
    const float* __restrict__ W0, const float* __restrict__ W1, const float* __restrict__ W2,
    const float* __restrict__ bi0, const float* __restrict__ bi1, const float* __restrict__ bi2,
    float* __restrict__ C0, float* __restrict__ C1, float* __restrict__ C2,
    int M, int N, int K, int relu)
{
    const int z = blockIdx.z;
    const float* W    = (z == 0) ? W0  : (z == 1) ? W1  : W2;
    const float* bias = (z == 0) ? bi0 : (z == 1) ? bi1 : bi2;
    float*       C    = (z == 0) ? C0  : (z == 1) ? C1  : C2;

    __shared__ float As[16][132];   // [k][m] (132*4=528B row stride, 16B-aligned)
    __shared__ float Ws[16][64];    // [k][n]
    const int t  = threadIdx.x;
    const int bm = blockIdx.x * 128, bn = blockIdx.y * 64;
    const int tx = t & 15, ty = t >> 4;            // n = tx*4, m = ty*8
    const int ar = t >> 1, ac = (t & 1) * 8;       // A load: row ar, k-offset ac
    const int wr = t >> 4, wc = (t & 15) * 4;      // W load

    unsigned long long acc[4][4];   // [m-pair][n]
#pragma unroll
    for (int i = 0; i < 4; i++)
#pragma unroll
        for (int j = 0; j < 4; j++) acc[i][j] = 0ULL;

    for (int k0 = 0; k0 < K; k0 += 16) {
        float4 a0 = *(const float4*)(A + (size_t)(bm + ar) * K + k0 + ac);
        float4 a1 = *(const float4*)(A + (size_t)(bm + ar) * K + k0 + ac + 4);
        float4 wv = *(const float4*)(W + (size_t)(k0 + wr) * N + bn + wc);
        As[ac + 0][ar] = a0.x; As[ac + 1][ar] = a0.y;
        As[ac + 2][ar] = a0.z; As[ac + 3][ar] = a0.w;
        As[ac + 4][ar] = a1.x; As[ac + 5][ar] = a1.y;
        As[ac + 6][ar] = a1.z; As[ac + 7][ar] = a1.w;
        *(float4*)(&Ws[wr][wc]) = wv;
        __syncthreads();
#pragma unroll
        for (int k = 0; k < 16; k++) {
            ulonglong2 am0 = *(const ulonglong2*)(&As[k][ty * 8]);      // m pairs 0,1
            ulonglong2 am1 = *(const ulonglong2*)(&As[k][ty * 8 + 4]);  // m pairs 2,3
            float4 w4 = *(const float4*)(&Ws[k][tx * 4]);
            unsigned long long wp0, wp1, wp2, wp3;
            PACK2(wp0, w4.x); PACK2(wp1, w4.y); PACK2(wp2, w4.z); PACK2(wp3, w4.w);
            FMA2(acc[0][0], am0.x, wp0); FMA2(acc[0][1], am0.x, wp1);
            FMA2(acc[0][2], am0.x, wp2); FMA2(acc[0][3], am0.x, wp3);
            FMA2(acc[1][0], am0.y, wp0); FMA2(acc[1][1], am0.y, wp1);
            FMA2(acc[1][2], am0.y, wp2); FMA2(acc[1][3], am0.y, wp3);
            FMA2(acc[2][0], am1.x, wp0); FMA2(acc[2][1], am1.x, wp1);
            FMA2(acc[2][2], am1.x, wp2); FMA2(acc[2][3], am1.x, wp3);
            FMA2(acc[3][0], am1.y, wp0); FMA2(acc[3][1], am1.y, wp1);
            FMA2(acc[3][2], am1.y, wp2); FMA2(acc[3][3], am1.y, wp3);
        }
        __syncthreads();
    }
    float b0 = bias[bn + tx * 4 + 0], b1 = bias[bn + tx * 4 + 1];
    float b2 = bias[bn + tx * 4 + 2], b3 = bias[bn + tx * 4 + 3];
#pragma unroll
    for (int mp = 0; mp < 4; mp++) {
        float4 lo, hi;
        lo.x = ull_lo(acc[mp][0]) + b0; lo.y = ull_lo(acc[mp][1]) + b1;
        lo.z = ull_lo(acc[mp][2]) + b2; lo.w = ull_lo(acc[mp][3]) + b3;
        hi.x = ull_hi(acc[mp][0]) + b0; hi.y = ull_hi(acc[mp][1]) + b1;
        hi.z = ull_hi(acc[mp][2]) + b2; hi.w = ull_hi(acc[mp][3]) + b3;
        if (relu) {
            lo.x = fmaxf(lo.x, 0.f); lo.y = fmaxf(lo.y, 0.f);
            lo.z = fmaxf(lo.z, 0.f); lo.w = fmaxf(lo.w, 0.f);
            hi.x = fmaxf(hi.x, 0.f); hi.y = fmaxf(hi.y, 0.f);
            hi.z = fmaxf(hi.z, 0.f); hi.w = fmaxf(hi.w, 0.f);
        }
        *(float4*)(C + (size_t)(bm + ty * 8 + 2 * mp + 0) * N + bn + tx * 4) = lo;
        *(float4*)(C + (size_t)(bm + ty * 8 + 2 * mp + 1) * N + bn + tx * 4) = hi;
    }
}

// ---------------------------------------------------------------------------
// Residual add + LayerNorm (D=256), one block per token, in-place into h
// ---------------------------------------------------------------------------
__global__ void add_ln_kernel(float* __restrict__ h, const float* __restrict__ t,
                              const float* __restrict__ g, const float* __restrict__ be) {
    __shared__ float red[8];
    const int row = blockIdx.x, i = threadIdx.x;
    const size_t base = (size_t)row * Dm;
    float v = h[base + i] + t[base + i];
    float s = v;
#pragma unroll
    for (int o = 16; o; o >>= 1) s += __shfl_xor_sync(0xffffffffu, s, o);
    if ((i & 31) == 0) red[i >> 5] = s;
    __syncthreads();
    float mean = 0.f;
#pragma unroll
    for (int k = 0; k < 8; k++) mean += red[k];
    mean *= (1.0f / Dm);
    __syncthreads();
    float d = v - mean;
    s = d * d;
#pragma unroll
    for (int o = 16; o; o >>= 1) s += __shfl_xor_sync(0xffffffffu, s, o);
    if ((i & 31) == 0) red[i >> 5] = s;
    __syncthreads();
    float var = 0.f;
#pragma unroll
    for (int k = 0; k < 8; k++) var += red[k];
    var *= (1.0f / Dm);
    h[base + i] = d * rsqrtf(var + 1e-5f) * g[i] + be[i];
}

// ---------------------------------------------------------------------------
// Attention: one CTA = (b, h, 16-query block), 512 threads (16 warps).
// Full 16 x Lseq logit rows in SMEM (stride LPAD2). Key chunks of 512 with
// register-prefetch software pipelining (LDG for chunk c+1 overlaps compute
// of chunk c). FFMA2 with naturally-paired operands; streaming stores for P.
// ---------------------------------------------------------------------------
__global__ __launch_bounds__(512) void attn_kernel(
    const float* __restrict__ Q, const float* __restrict__ K,
    const float* __restrict__ V, float* __restrict__ P, float* __restrict__ O)
{
    extern __shared__ float sm[];
    float* sQ   = sm;                  // [16 q][32 e]
    float* sKV  = sm + 512;            // K [512][32] swizzled / V [32][512] swizzled
    float* sL   = sm + 512 + 16384;    // 16 rows, stride LPAD2 (probs, unnormalized)
    float* sInv = sL + 16 * LPAD2;     // [16] 1/rowsum

    const int tid  = threadIdx.x;
    const int warp = tid >> 5, lane = tid & 31;
    const int qb = blockIdx.x, hh = blockIdx.y, b = blockIdx.z;
    const int l0 = qb * 16;
    const float* qptr = Q + (size_t)b * Lseq * 128 + hh * 32;
    const float* kptr = K + (size_t)b * Lseq * 128 + hh * 32;
    const float* vptr = V + (size_t)b * Lseq * 128 + hh * 32;

    // ---- load Q natural [q][e] (512 threads exactly) ----
    sQ[tid] = qptr[(size_t)(l0 + warp) * 128 + lane];

    // ---- logits: S = Q K^T * scale (e-paired FFMA2, prefetch-pipelined) ----
    {
        const int qg = warp & 3;       // q rows qg*4 .. qg*4+3
        const int kh = warp >> 2;      // 128-j block within chunk
        const int jbase = kh * 128 + lane;
        const int pr = tid >> 3, pe4 = tid & 7;     // prefetch row/e-group

        float4 pf[8];
#pragma unroll
        for (int s = 0; s < 8; s++) {               // prefetch chunk 0
            int r = pr + s * 64;
            pf[s] = (r < Lseq)
                ? *(const float4*)(kptr + (size_t)r * 128 + pe4 * 4)
                : make_float4(0.f, 0.f, 0.f, 0.f);
        }
        for (int j0 = 0; j0 < Lseq; j0 += CH) {
            __syncthreads();
            // store prefetched chunk into smem (XOR-swizzled float4 groups)
#pragma unroll
            for (int s = 0; s < 8; s++) {
                int r = pr + s * 64;
                *(float4*)(sKV + r * 32 + ((pe4 ^ (r & 7)) << 2)) = pf[s];
            }
            // prefetch next chunk (LDGs overlap the compute below)
            if (j0 + CH < Lseq) {
#pragma unroll
                for (int s = 0; s < 8; s++) {
                    int r = j0 + CH + pr + s * 64;
                    pf[s] = (r < Lseq)
                        ? *(const float4*)(kptr + (size_t)r * 128 + pe4 * 4)
                        : make_float4(0.f, 0.f, 0.f, 0.f);
                }
            }
            __syncthreads();
            unsigned long long acc[4][4];
#pragma unroll
            for (int qq = 0; qq < 4; qq++)
#pragma unroll
                for (int c = 0; c < 4; c++) acc[qq][c] = 0ULL;
#pragma unroll
            for (int e4 = 0; e4 < 8; e4++) {
                ulonglong2 qp[4];
#pragma unroll
                for (int qq = 0; qq < 4; qq++)
                    qp[qq] = *(const ulonglong2*)(sQ + (qg * 4 + qq) * 32 + e4 * 4);
#pragma unroll
                for (int c = 0; c < 4; c++) {
                    const int j = jbase + 32 * c;
                    ulonglong2 kp = *(const ulonglong2*)(sKV + j * 32 + ((e4 ^ (j & 7)) << 2));
#pragma unroll
                    for (int qq = 0; qq < 4; qq++) {
                        FMA2(acc[qq][c], qp[qq].x, kp.x);
                        FMA2(acc[qq][c], qp[qq].y, kp.y);
                    }
                }
            }
#pragma unroll
            for (int qq = 0; qq < 4; qq++)
#pragma unroll
                for (int c = 0; c < 4; c++) {
                    float s = (ull_lo(acc[qq][c]) + ull_hi(acc[qq][c])) * QSCALE;
                    sL[(size_t)(qg * 4 + qq) * LPAD2 + j0 + jbase + 32 * c] = s;
                }
        }
    }
    __syncthreads();

    // ---- softmax per row (warp w owns row w); keep UNNORMALIZED p in smem ----
    {
        float* row = sL + (size_t)warp * LPAD2;
        float m = -1e30f;
        for (int j = lane; j < Lseq; j += 32) m = fmaxf(m, row[j]);
#pragma unroll
        for (int o = 16; o; o >>= 1) m = fmaxf(m, __shfl_xor_sync(0xffffffffu, m, o));
        float s = 0.f;
        for (int j = lane; j < Lseq; j += 32) {
            float p = __expf(row[j] - m);
            row[j] = p; s += p;
        }
#pragma unroll
        for (int o = 16; o; o >>= 1) s += __shfl_xor_sync(0xffffffffu, s, o);
        const float inv = 1.0f / s;
        if (lane == 0) sInv[warp] = inv;
        float* grow = P + (((size_t)b * Hh + hh) * Lseq + (l0 + warp)) * (size_t)Lseq;
        for (int j = lane; j < Lseq; j += 32)
            __stcs(grow + j, row[j] * inv);       // streaming: don't pollute L2
    }

    // ---- O = P @ V (j-paired FFMA2, V transposed [d][j] swizzled, pipelined) ----
    const int qg2 = warp >> 2;        // q rows qg2*4 .. +3
    const int jh  = warp & 3;         // 128-j block within chunk
    const int m8  = lane & 7;         // d group: d = m8*4 + cc
    const int jq  = lane >> 3;        // j stagger 0..3
    const int pr = tid >> 3, pdg = tid & 7;
    unsigned long long acc[4][4];
#pragma unroll
    for (int qq = 0; qq < 4; qq++)
#pragma unroll
        for (int cc = 0; cc < 4; cc++) acc[qq][cc] = 0ULL;

    float4 pf[8];
#pragma unroll
    for (int s = 0; s < 8; s++) {                 // prefetch chunk 0
        int r = pr + s * 64;
        pf[s] = (r < Lseq)
            ? *(const float4*)(vptr + (size_t)r * 128 + pdg * 4)
            : make_float4(0.f, 0.f, 0.f, 0.f);
    }
    for (int j0 = 0; j0 < Lseq; j0 += CH) {
        __syncthreads();
        // store V chunk transposed: (d, j) at d*512 + ((j>>2 ^ dg)*4 + (j&3))
#pragma unroll
        for (int s = 0; s < 8; s++) {
            int r = pr + s * 64;
            int r4 = r >> 2, rl = r & 3;
            int swb = ((r4 ^ pdg) << 2) + rl;
            sKV[(pdg * 4 + 0) * 512 + swb] = pf[s].x;
            sKV[(pdg * 4 + 1) * 512 + swb] = pf[s].y;
            sKV[(pdg * 4 + 2) * 512 + swb] = pf[s].z;
            sKV[(pdg * 4 + 3) * 512 + swb] = pf[s].w;
        }
        if (j0 + CH < Lseq) {
#pragma unroll
            for (int s = 0; s < 8; s++) {
                int r = j0 + CH + pr + s * 64;
                pf[s] = (r < Lseq)
                    ? *(const float4*)(vptr + (size_t)r * 128 + pdg * 4)
                    : make_float4(0.f, 0.f, 0.f, 0.f);
            }
        }
        __syncthreads();
#pragma unroll
        for (int i = 0; i < 8; i++) {
            const int j = jh * 128 + i * 16 + jq * 4;
            const int j4 = j >> 2;
            ulonglong2 pp[4];
#pragma unroll
            for (int qq = 0; qq < 4; qq++)
                pp[qq] = *(const ulonglong2*)(sL + (size_t)(qg2 * 4 + qq) * LPAD2 + j0 + j);
#pragma unroll
            for (int cc = 0; cc < 4; cc++) {
                const int d = m8 * 4 + cc;
                ulonglong2 vp = *(const ulonglong2*)(sKV + d * 512 + ((j4 ^ m8) << 2));
#pragma unroll
                for (int qq = 0; qq < 4; qq++) {
                    FMA2(acc[qq][cc], pp[qq].x, vp.x);
                    FMA2(acc[qq][cc], pp[qq].y, vp.y);
                }
            }
        }
    }
    // horizontal (even/odd j halves) + reduce across jq via shuffles
    float part[4][4];
#pragma unroll
    for (int qq = 0; qq < 4; qq++)
#pragma unroll
        for (int cc = 0; cc < 4; cc++) {
            float p = ull_lo(acc[qq][cc]) + ull_hi(acc[qq][cc]);
            p += __shfl_xor_sync(0xffffffffu, p, 8);
            p += __shfl_xor_sync(0xffffffffu, p, 16);
            part[qq][cc] = p;
        }
    __syncthreads();   // done reading sKV (V) and sL
    if (jq == 0) {     // lanes 0..7 hold jq-reduced partials; write per-jh partials
#pragma unroll
        for (int qq = 0; qq < 4; qq++)
#pragma unroll
            for (int cc = 0; cc < 4; cc++)
                sKV[jh * 512 + (qg2 * 4 + qq) * 32 + m8 * 4 + cc] = part[qq][cc];
    }
    __syncthreads();
    {
        const int q = warp;        // 16 warps -> 16 q rows, d = lane
        float o = sKV[0 * 512 + q * 32 + lane] + sKV[1 * 512 + q * 32 + lane] +
                  sKV[2 * 512 + q * 32 + lane] + sKV[3 * 512 + q * 32 + lane];
        o *= sInv[q];
        O[(size_t)(b * Lseq + l0 + q) * 128 + hh * 32 + lane] = o;
    }
}

// ---------------------------------------------------------------------------
// Final head: out = t2 @ o2w + o2b   (N=2, K=256)
// ---------------------------------------------------------------------------
__global__ void head_kernel(const float* __restrict__ t2, const float* __restrict__ w,
                            const float* __restrict__ b, float* __restrict__ out) {
    int idx = blockIdx.x * 256 + threadIdx.x;
    if (idx >= MTOK * 2) return;
    int tok = idx >> 1, j = idx & 1;
    const float* a = t2 + (size_t)tok * 256;
    float acc = b[j];
#pragma unroll 8
    for (int k = 0; k < 256; k++) acc = fmaf(a[k], w[k * 2 + j], acc);
    out[idx] = acc;
}

// ---------------------------------------------------------------------------
// Driver
// ---------------------------------------------------------------------------
extern "C" void kernel_launch(void* const* d_in, const int* in_sizes, int n_in,
                              void* d_out, int out_size) {
    const float* x    = (const float*)d_in[0];
    const float* in_w = (const float*)d_in[1];
    const float* in_b = (const float*)d_in[2];
    const float* qw   = (const float*)d_in[3];
    const float* qb   = (const float*)d_in[4];
    const float* kw   = (const float*)d_in[5];
    const float* kb   = (const float*)d_in[6];
    const float* vw   = (const float*)d_in[7];
    const float* vb   = (const float*)d_in[8];
    const float* ow   = (const float*)d_in[9];
    const float* ob   = (const float*)d_in[10];
    const float* f1w  = (const float*)d_in[11];
    const float* f1b  = (const float*)d_in[12];
    const float* f2w  = (const float*)d_in[13];
    const float* f2b  = (const float*)d_in[14];
    const float* n1g  = (const float*)d_in[15];
    const float* n1b  = (const float*)d_in[16];
    const float* n2g  = (const float*)d_in[17];
    const float* n2b  = (const float*)d_in[18];
    const float* o1w  = (const float*)d_in[19];
    const float* o1b  = (const float*)d_in[20];
    const float* o2w  = (const float*)d_in[21];
    const float* o2b  = (const float*)d_in[22];
    float* out = (float*)d_out;

    float *h, *Qb, *Kb, *Vb, *Ob, *Tb, *Fb;
    cudaGetSymbolAddress((void**)&h,  g_h);
    cudaGetSymbolAddress((void**)&Qb, g_q);
    cudaGetSymbolAddress((void**)&Kb, g_k);
    cudaGetSymbolAddress((void**)&Vb, g_v);
    cudaGetSymbolAddress((void**)&Ob, g_o);
    cudaGetSymbolAddress((void**)&Tb, g_t);
    cudaGetSymbolAddress((void**)&Fb, g_f);

    const size_t smem_bytes = ATTN_SMEM_FLOATS * sizeof(float);
    cudaFuncSetAttribute(attn_kernel, cudaFuncAttributeMaxDynamicSharedMemorySize,
                         (int)smem_bytes);

    const int M = MTOK;
    inproj_kernel<<<(M * Dm + 255) / 256, 256>>>(x, in_w, in_b, h);

    const size_t ATTN_L = (size_t)8 * Hh * Lseq * Lseq;  // per-layer attns size
    for (int i = 0; i < 3; i++) {
        const float* qwi = qw + (size_t)i * 256 * 128;
        const float* kwi = kw + (size_t)i * 256 * 128;
        const float* vwi = vw + (size_t)i * 256 * 128;
        sgemm_kernel<<<dim3(M / 128, 2, 3), 256>>>(
            h, qwi, kwi, vwi, qb + i * 128, kb + i * 128, vb + i * 128,
            Qb, Kb, Vb, M, 128, 256, 0);

        attn_kernel<<<dim3(Lseq / 16, Hh, 8), 512, smem_bytes>>>(
            Qb, Kb, Vb, out + 32256 + (size_t)i * ATTN_L, Ob);

        const float* owi = ow + (size_t)i * 128 * 256;
        sgemm_kernel<<<dim3(M / 128, 4, 1), 256>>>(
            Ob, owi, owi, owi, ob + i * 256, ob + i * 256, ob + i * 256,
            Tb, Tb, Tb, M, 256, 128, 0);
        add_ln_kernel<<<M, 256>>>(h, Tb, n1g + i * 256, n1b + i * 256);

        const float* f1wi = f1w + (size_t)i * 256 * 64;
        sgemm_kernel<<<dim3(M / 128, 1, 1), 256>>>(
            h, f1wi, f1wi, f1wi, f1b + i * 64, f1b + i * 64, f1b + i * 64,
            Fb, Fb, Fb, M, 64, 256, 1);
        const float* f2wi = f2w + (size_t)i * 64 * 256;
        sgemm_kernel<<<dim3(M / 128, 4, 1), 256>>>(
            Fb, f2wi, f2wi, f2wi, f2b + i * 256, f2b + i * 256, f2b + i * 256,
            Tb, Tb, Tb, M, 256, 64, 0);
        add_ln_kernel<<<M, 256>>>(h, Tb, n2g + i * 256, n2b + i * 256);
    }

    sgemm_kernel<<<dim3(M / 128, 4, 1), 256>>>(
        h, o1w, o1w, o1w, o1b, o1b, o1b, Tb, Tb, Tb, M, 256, 256, 1);
    head_kernel<<<(M * 2 + 255) / 256, 256>>>(Tb, o2w, o2b, out);
}